// round 4
// baseline (speedup 1.0000x reference)
#include <cuda_runtime.h>
#include <cuda_bf16.h>
#include <cstdint>

#define TT 512
#define BB 128
#define HH 512
#define G4 2048

typedef unsigned long long ull;

__device__ float g_xg[(size_t)TT * BB * G4];
__device__ float g_hs[(size_t)TT * BB * HH];
__device__ float g_r[(size_t)BB * HH];
__device__ float g_e[(size_t)TT * BB];
__device__ unsigned g_bar;

__device__ __forceinline__ ull fma2(ull a, ull b, ull c) {
    ull d; asm("fma.rn.f32x2 %0, %1, %2, %3;" : "=l"(d) : "l"(a), "l"(b), "l"(c)); return d;
}
__device__ __forceinline__ ull pack2(float x, float y) {
    ull r; asm("mov.b64 %0, {%1, %2};" : "=l"(r) : "f"(x), "f"(y)); return r;
}
__device__ __forceinline__ float2 unpack2(ull v) {
    float2 f; asm("mov.b64 {%0, %1}, %2;" : "=f"(f.x), "=f"(f.y) : "l"(v)); return f;
}

__global__ void k_init(float* e) {
    int i = blockIdx.x * 256 + threadIdx.x;
    if (i < TT * BB) e[i] = 0.f;
    if (i == 0) g_bar = 0u;
}

// ---- xg[t*128+b][g] = x[b][t][:] @ W_ih[g][:] + bias[g] ----
__global__ __launch_bounds__(256) void k_xg(
    const float* __restrict__ x, const float* __restrict__ Wih,
    const float* __restrict__ bih, const float* __restrict__ bhh,
    float* __restrict__ xg)
{
    __shared__ float As[8][132];
    __shared__ float Bs[8][132];
    const int tid = threadIdx.x;
    const int tx = tid & 15, ty = tid >> 4;
    const int mBase = blockIdx.y * 128, nBase = blockIdx.x * 128;
    const int lr = tid >> 1, lk = (tid & 1) * 4;
    const int m = mBase + lr;
    const float* aptr = x + ((size_t)(m & 127) * TT + (m >> 7)) * HH + lk;
    const float* bptr = Wih + (size_t)(nBase + lr) * HH + lk;

    ull acc[8][4];
#pragma unroll
    for (int i = 0; i < 8; i++)
#pragma unroll
        for (int j = 0; j < 4; j++) acc[i][j] = 0ull;

    for (int k0 = 0; k0 < HH; k0 += 8) {
        float4 av = *(const float4*)(aptr + k0);
        float4 bv = *(const float4*)(bptr + k0);
        __syncthreads();
        As[lk + 0][lr] = av.x; As[lk + 1][lr] = av.y; As[lk + 2][lr] = av.z; As[lk + 3][lr] = av.w;
        Bs[lk + 0][lr] = bv.x; Bs[lk + 1][lr] = bv.y; Bs[lk + 2][lr] = bv.z; Bs[lk + 3][lr] = bv.w;
        __syncthreads();
#pragma unroll
        for (int k = 0; k < 8; k++) {
            float4 a0 = *(const float4*)&As[k][ty * 8];
            float4 a1 = *(const float4*)&As[k][ty * 8 + 4];
            ulonglong2 b0 = *(const ulonglong2*)&Bs[k][tx * 8];
            ulonglong2 b1 = *(const ulonglong2*)&Bs[k][tx * 8 + 4];
            float af[8] = {a0.x, a0.y, a0.z, a0.w, a1.x, a1.y, a1.z, a1.w};
            ull bp[4] = {b0.x, b0.y, b1.x, b1.y};
#pragma unroll
            for (int i = 0; i < 8; i++) {
                ull ap = pack2(af[i], af[i]);
#pragma unroll
                for (int j = 0; j < 4; j++) acc[i][j] = fma2(ap, bp[j], acc[i][j]);
            }
        }
    }
    const int gc = nBase + tx * 8;
    float bias[8];
#pragma unroll
    for (int j = 0; j < 8; j++) bias[j] = bih[gc + j] + bhh[gc + j];
#pragma unroll
    for (int i = 0; i < 8; i++) {
        float2 v0 = unpack2(acc[i][0]), v1 = unpack2(acc[i][1]);
        float2 v2 = unpack2(acc[i][2]), v3 = unpack2(acc[i][3]);
        float* orow = xg + (size_t)(mBase + ty * 8 + i) * G4 + gc;
        *(float4*)orow = make_float4(v0.x + bias[0], v0.y + bias[1], v1.x + bias[2], v1.y + bias[3]);
        *((float4*)orow + 1) = make_float4(v2.x + bias[4], v2.y + bias[5], v3.x + bias[6], v3.y + bias[7]);
    }
}

// ---- persistent LSTM recurrence: 128 CTAs, CTA bx owns h-cols [bx*4, bx*4+4) ----
__global__ __launch_bounds__(256) void k_lstm(
    const float* __restrict__ Whh, const float* __restrict__ xg,
    float* __restrict__ hs)
{
    extern __shared__ float sm[];
    float (*w_s)[512] = (float(*)[512])sm;               // 16 x 512
    float (*h_s)[132] = (float(*)[132])(sm + 16 * 512);  // 128 x 132

    const int tid = threadIdx.x;
    const int bx = blockIdx.x;
    const int b = tid >> 1;
    const int half = tid & 1;
    const int w8 = half * 8;

    for (int i = tid; i < 16 * 512; i += 256) {
        int q = i >> 9, k = i & 511;
        int row = (q & 3) * HH + bx * 4 + (q >> 2);
        w_s[q][k] = Whh[(size_t)row * HH + k];
    }
    float c0 = 0.f, c1 = 0.f;
    __syncthreads();

    for (int t = 0; t < TT; t++) {
        const float* xgp = xg + ((size_t)t * BB + b) * G4;
        float xv[8];
#pragma unroll
        for (int jl = 0; jl < 2; jl++)
#pragma unroll
            for (int g = 0; g < 4; g++)
                xv[jl * 4 + g] = __ldcg(xgp + g * HH + bx * 4 + half * 2 + jl);

        ull acc2[8];
#pragma unroll
        for (int q = 0; q < 8; q++) acc2[q] = 0ull;

        if (t > 0) {
            const float* hsrc = hs + (size_t)(t - 1) * BB * HH;
            for (int k0 = 0; k0 < HH; k0 += 128) {
                __syncthreads();
                for (int i = tid; i < 128 * 32; i += 256) {
                    int bl = i >> 5, k4 = (i & 31) << 2;
                    float4 v = __ldcg((const float4*)(hsrc + (size_t)bl * HH + k0 + k4));
                    *(float4*)&h_s[bl][k4] = v;
                }
                __syncthreads();
#pragma unroll 4
                for (int k = 0; k < 128; k += 4) {
                    ulonglong2 hv = *(const ulonglong2*)&h_s[b][k];
#pragma unroll
                    for (int q8 = 0; q8 < 8; q8++) {
                        ulonglong2 wv = *(const ulonglong2*)&w_s[w8 + q8][k0 + k];
                        acc2[q8] = fma2(wv.x, hv.x, acc2[q8]);
                        acc2[q8] = fma2(wv.y, hv.y, acc2[q8]);
                    }
                }
            }
        }

        float h0, h1;
        {
            float2 p;
            p = unpack2(acc2[0]); float gi = p.x + p.y + xv[0];
            p = unpack2(acc2[1]); float gf = p.x + p.y + xv[1];
            p = unpack2(acc2[2]); float gg = p.x + p.y + xv[2];
            p = unpack2(acc2[3]); float go = p.x + p.y + xv[3];
            float si = 1.f / (1.f + expf(-gi)), sf = 1.f / (1.f + expf(-gf));
            float so = 1.f / (1.f + expf(-go));
            c0 = sf * c0 + si * tanhf(gg);
            h0 = so * tanhf(c0);
            p = unpack2(acc2[4]); gi = p.x + p.y + xv[4];
            p = unpack2(acc2[5]); gf = p.x + p.y + xv[5];
            p = unpack2(acc2[6]); gg = p.x + p.y + xv[6];
            p = unpack2(acc2[7]); go = p.x + p.y + xv[7];
            si = 1.f / (1.f + expf(-gi)); sf = 1.f / (1.f + expf(-gf));
            so = 1.f / (1.f + expf(-go));
            c1 = sf * c1 + si * tanhf(gg);
            h1 = so * tanhf(c1);
        }
        float* hdst = hs + ((size_t)t * BB + b) * HH + bx * 4 + half * 2;
        __stcg(hdst, h0);
        __stcg(hdst + 1, h1);

        __syncthreads();
        if (tid == 0) {
            __threadfence();
            atomicAdd(&g_bar, 1u);
            unsigned tgt = 128u * (unsigned)(t + 1);
            while (*((volatile unsigned*)&g_bar) < tgt) __nanosleep(32);
            __threadfence();
        }
        __syncthreads();
    }
}

// ---- r[b][g] = h_last[b][:] @ U1[g][512:1024] ----
__global__ __launch_bounds__(256) void k_r(
    const float* __restrict__ hs, const float* __restrict__ U1, float* __restrict__ r)
{
    __shared__ float hl[512];
    const int b = blockIdx.x, tid = threadIdx.x;
    for (int i = tid; i < 512; i += 256)
        hl[i] = hs[((size_t)(TT - 1) * BB + b) * HH + i];
    __syncthreads();
    for (int g = tid; g < 512; g += 256) {
        const float* up = U1 + (size_t)g * 1024 + 512;
        float acc = 0.f;
        for (int k = 0; k < 512; k += 4) {
            float4 u = *(const float4*)(up + k);
            acc += hl[k] * u.x + hl[k+1] * u.y + hl[k+2] * u.z + hl[k+3] * u.w;
        }
        r[(size_t)b * HH + g] = acc;
    }
}

// ---- e[m] += sum_g tanh(hs@U1a + x@U2 + r) * Ve[g]  (atomic over 4 N-blocks) ----
__global__ __launch_bounds__(256) void k_e(
    const float* __restrict__ hs, const float* __restrict__ x,
    const float* __restrict__ U1, const float* __restrict__ U2,
    const float* __restrict__ r, const float* __restrict__ Ve,
    float* __restrict__ e)
{
    __shared__ float As[8][132];
    __shared__ float Bs[8][132];
    const int tid = threadIdx.x;
    const int tx = tid & 15, ty = tid >> 4;
    const int mBase = blockIdx.y * 128, nBase = blockIdx.x * 128;
    const int lr = tid >> 1, lk = (tid & 1) * 4;
    const int m = mBase + lr;
    const float* aptrs[2] = { hs + (size_t)m * HH + lk,
                              x + ((size_t)(m & 127) * TT + (m >> 7)) * HH + lk };
    const float* bptrs[2] = { U1 + (size_t)(nBase + lr) * 1024 + lk,
                              U2 + (size_t)(nBase + lr) * 512 + lk };

    ull acc[8][4];
#pragma unroll
    for (int i = 0; i < 8; i++)
#pragma unroll
        for (int j = 0; j < 4; j++) acc[i][j] = 0ull;

    for (int ph = 0; ph < 2; ph++) {
        const float* ap = aptrs[ph];
        const float* bp_ = bptrs[ph];
        for (int k0 = 0; k0 < HH; k0 += 8) {
            float4 av = *(const float4*)(ap + k0);
            float4 bv = *(const float4*)(bp_ + k0);
            __syncthreads();
            As[lk + 0][lr] = av.x; As[lk + 1][lr] = av.y; As[lk + 2][lr] = av.z; As[lk + 3][lr] = av.w;
            Bs[lk + 0][lr] = bv.x; Bs[lk + 1][lr] = bv.y; Bs[lk + 2][lr] = bv.z; Bs[lk + 3][lr] = bv.w;
            __syncthreads();
#pragma unroll
            for (int k = 0; k < 8; k++) {
                float4 a0 = *(const float4*)&As[k][ty * 8];
                float4 a1 = *(const float4*)&As[k][ty * 8 + 4];
                ulonglong2 b0 = *(const ulonglong2*)&Bs[k][tx * 8];
                ulonglong2 b1 = *(const ulonglong2*)&Bs[k][tx * 8 + 4];
                float af[8] = {a0.x, a0.y, a0.z, a0.w, a1.x, a1.y, a1.z, a1.w};
                ull bp2[4] = {b0.x, b0.y, b1.x, b1.y};
#pragma unroll
                for (int i = 0; i < 8; i++) {
                    ull apk = pack2(af[i], af[i]);
#pragma unroll
                    for (int j = 0; j < 4; j++) acc[i][j] = fma2(apk, bp2[j], acc[i][j]);
                }
            }
        }
    }

    const int gc = nBase + tx * 8;
    float ve[8];
#pragma unroll
    for (int j = 0; j < 8; j++) ve[j] = Ve[gc + j];
#pragma unroll
    for (int i = 0; i < 8; i++) {
        const int brow = ty * 8 + i;           // batch index (mBase % 128 == 0)
        const float* rr = r + (size_t)brow * HH + gc;
        float si = 0.f; float2 v;
        v = unpack2(acc[i][0]); si += tanhf(v.x + rr[0]) * ve[0] + tanhf(v.y + rr[1]) * ve[1];
        v = unpack2(acc[i][1]); si += tanhf(v.x + rr[2]) * ve[2] + tanhf(v.y + rr[3]) * ve[3];
        v = unpack2(acc[i][2]); si += tanhf(v.x + rr[4]) * ve[4] + tanhf(v.y + rr[5]) * ve[5];
        v = unpack2(acc[i][3]); si += tanhf(v.x + rr[6]) * ve[6] + tanhf(v.y + rr[7]) * ve[7];
#pragma unroll
        for (int o = 8; o >= 1; o >>= 1)
            si += __shfl_xor_sync(0xffffffffu, si, o, 16);
        if (tx == 0) atomicAdd(&e[mBase + ty * 8 + i], si);
    }
}

// ---- softmax over t, context, output head; one CTA per batch element ----
__global__ __launch_bounds__(256) void k_final(
    const float* __restrict__ hs, const float* __restrict__ e,
    const float* __restrict__ Wout, const float* __restrict__ bout,
    float* __restrict__ out)
{
    __shared__ float al[512];
    __shared__ float red[256];
    const int b = blockIdx.x, tid = threadIdx.x;

    float ev0 = e[(size_t)tid * BB + b];
    float ev1 = e[(size_t)(tid + 256) * BB + b];

    red[tid] = fmaxf(ev0, ev1);
    __syncthreads();
    for (int s = 128; s > 0; s >>= 1) {
        if (tid < s) red[tid] = fmaxf(red[tid], red[tid + s]);
        __syncthreads();
    }
    float mx = red[0];
    __syncthreads();
    float x0 = expf(ev0 - mx), x1 = expf(ev1 - mx);
    red[tid] = x0 + x1;
    __syncthreads();
    for (int s = 128; s > 0; s >>= 1) {
        if (tid < s) red[tid] += red[tid + s];
        __syncthreads();
    }
    float inv = 1.f / red[0];
    al[tid] = x0 * inv;
    al[tid + 256] = x1 * inv;
    __syncthreads();

    // context: this thread owns h-cols tid and tid+256
    float ctx0 = 0.f, ctx1 = 0.f;
    for (int t = 0; t < TT; t++) {
        float a = al[t];
        const float* hp = hs + ((size_t)t * BB + b) * HH;
        ctx0 += a * hp[tid];
        ctx1 += a * hp[tid + 256];
    }

    // params = context @ W_out^T + b_out
    float p0 = ctx0 * Wout[tid] + ctx1 * Wout[tid + 256];
    float p1 = ctx0 * Wout[512 + tid] + ctx1 * Wout[512 + tid + 256];
    red[tid] = p0;
    __syncthreads();
    for (int s = 128; s > 0; s >>= 1) {
        if (tid < s) red[tid] += red[tid + s];
        __syncthreads();
    }
    float mu = red[0] + bout[0];
    __syncthreads();
    red[tid] = p1;
    __syncthreads();
    for (int s = 128; s > 0; s >>= 1) {
        if (tid < s) red[tid] += red[tid + s];
        __syncthreads();
    }
    if (tid == 0) {
        float pv = red[0] + bout[1];
        float sp = (pv > 20.f) ? pv : log1pf(expf(pv));
        out[b] = mu;
        out[BB + b] = sp + 1e-5f;
    }
}

extern "C" void kernel_launch(void* const* d_in, const int* in_sizes, int n_in,
                              void* d_out, int out_size) {
    const float* x    = (const float*)d_in[0];
    const float* Wih  = (const float*)d_in[1];
    const float* Whh  = (const float*)d_in[2];
    const float* bih  = (const float*)d_in[3];
    const float* bhh  = (const float*)d_in[4];
    const float* Ve   = (const float*)d_in[5];
    const float* U1   = (const float*)d_in[6];
    const float* U2   = (const float*)d_in[7];
    const float* Wout = (const float*)d_in[8];
    const float* bout = (const float*)d_in[9];
    float* out = (float*)d_out;

    float *xg, *hs, *r, *e;
    cudaGetSymbolAddress((void**)&xg, g_xg);
    cudaGetSymbolAddress((void**)&hs, g_hs);
    cudaGetSymbolAddress((void**)&r,  g_r);
    cudaGetSymbolAddress((void**)&e,  g_e);

    static bool attr_set = false;
    if (!attr_set) {
        cudaFuncSetAttribute(k_lstm, cudaFuncAttributeMaxDynamicSharedMemorySize, 101376);
        attr_set = true;
    }

    k_init<<<(TT * BB + 255) / 256, 256>>>(e);
    {
        dim3 g(G4 / 128, (TT * BB) / 128);
        k_xg<<<g, 256>>>(x, Wih, bih, bhh, xg);
    }
    k_lstm<<<128, 256, 101376>>>(Whh, xg, hs);
    k_r<<<BB, 256>>>(hs, U1, r);
    {
        dim3 g(HH / 128, (TT * BB) / 128);
        k_e<<<g, 256>>>(hs, x, U1, U2, r, Ve, e);
    }
    k_final<<<BB, 256>>>(hs, e, Wout, bout, out);
}

// round 5
// speedup vs baseline: 1.1236x; 1.1236x over previous
#include <cuda_runtime.h>
#include <cuda_bf16.h>
#include <cstdint>

#define TT 512
#define BB 128
#define HH 512
#define G4 2048

typedef unsigned long long ull;

__device__ float g_xg[(size_t)TT * G4 * BB];   // [t][g][b]
__device__ float g_hs[(size_t)TT * BB * HH];   // [t][b][h]
__device__ float g_r[(size_t)BB * HH];
__device__ float g_e[(size_t)TT * BB];
__device__ unsigned g_flags[128 * 32];         // one padded slot per CTA

__device__ __forceinline__ ull fma2(ull a, ull b, ull c) {
    ull d; asm("fma.rn.f32x2 %0, %1, %2, %3;" : "=l"(d) : "l"(a), "l"(b), "l"(c)); return d;
}
__device__ __forceinline__ ull pack2(float x, float y) {
    ull r; asm("mov.b64 %0, {%1, %2};" : "=l"(r) : "f"(x), "f"(y)); return r;
}
__device__ __forceinline__ float2 unpack2(ull v) {
    float2 f; asm("mov.b64 {%0, %1}, %2;" : "=f"(f.x), "=f"(f.y) : "l"(v)); return f;
}

__global__ void k_init(float* e) {
    int i = blockIdx.x * 256 + threadIdx.x;
    if (i < TT * BB) e[i] = 0.f;
    if (i < 128 * 32) g_flags[i] = 0u;
}

// ---- xg[t][g][b] = x[b][t][:] @ W_ih[g][:] + bias[g].  tile: one t, 128 b x 128 g ----
__global__ __launch_bounds__(256, 2) void k_xg(
    const float* __restrict__ x, const float* __restrict__ Wih,
    const float* __restrict__ bih, const float* __restrict__ bhh,
    float* __restrict__ xg)
{
    __shared__ float As[2][8][132];
    __shared__ float Bs[2][8][132];
    extern __shared__ float slab[];   // 128*129
    const int tid = threadIdx.x;
    const int tx = tid & 15, ty = tid >> 4;
    const int tBlk = blockIdx.y, nBase = blockIdx.x * 128;
    const int lr = tid >> 1, lk = (tid & 1) * 4;
    const float* aptr = x + ((size_t)lr * TT + tBlk) * HH + lk;       // b = lr
    const float* bptr = Wih + (size_t)(nBase + lr) * HH + lk;

    ull acc[8][4];
#pragma unroll
    for (int i = 0; i < 8; i++)
#pragma unroll
        for (int j = 0; j < 4; j++) acc[i][j] = 0ull;

    {
        float4 av = *(const float4*)aptr;
        float4 bv = *(const float4*)bptr;
        As[0][lk+0][lr]=av.x; As[0][lk+1][lr]=av.y; As[0][lk+2][lr]=av.z; As[0][lk+3][lr]=av.w;
        Bs[0][lk+0][lr]=bv.x; Bs[0][lk+1][lr]=bv.y; Bs[0][lk+2][lr]=bv.z; Bs[0][lk+3][lr]=bv.w;
    }
    __syncthreads();
    int buf = 0;

    for (int k0 = 0; k0 < HH; k0 += 8) {
        const bool more = (k0 + 8) < HH;
        float4 av2, bv2;
        if (more) {
            av2 = *(const float4*)(aptr + k0 + 8);
            bv2 = *(const float4*)(bptr + k0 + 8);
        }
#pragma unroll
        for (int k = 0; k < 8; k++) {
            float4 a0 = *(const float4*)&As[buf][k][ty * 8];
            float4 a1 = *(const float4*)&As[buf][k][ty * 8 + 4];
            ulonglong2 b0 = *(const ulonglong2*)&Bs[buf][k][tx * 8];
            ulonglong2 b1 = *(const ulonglong2*)&Bs[buf][k][tx * 8 + 4];
            float af[8] = {a0.x, a0.y, a0.z, a0.w, a1.x, a1.y, a1.z, a1.w};
            ull bp[4] = {b0.x, b0.y, b1.x, b1.y};
#pragma unroll
            for (int i = 0; i < 8; i++) {
                ull ap = pack2(af[i], af[i]);
#pragma unroll
                for (int j = 0; j < 4; j++) acc[i][j] = fma2(ap, bp[j], acc[i][j]);
            }
        }
        if (more) {
            int nb = buf ^ 1;
            As[nb][lk+0][lr]=av2.x; As[nb][lk+1][lr]=av2.y; As[nb][lk+2][lr]=av2.z; As[nb][lk+3][lr]=av2.w;
            Bs[nb][lk+0][lr]=bv2.x; Bs[nb][lk+1][lr]=bv2.y; Bs[nb][lk+2][lr]=bv2.z; Bs[nb][lk+3][lr]=bv2.w;
        }
        __syncthreads();
        buf ^= 1;
    }

    // transpose epilogue -> slab[g_local][b]
    const int gc = nBase + tx * 8;
    float bias[8];
#pragma unroll
    for (int j = 0; j < 8; j++) bias[j] = bih[gc + j] + bhh[gc + j];
#pragma unroll
    for (int i = 0; i < 8; i++) {
        const int br = ty * 8 + i;
        float2 v0 = unpack2(acc[i][0]), v1 = unpack2(acc[i][1]);
        float2 v2 = unpack2(acc[i][2]), v3 = unpack2(acc[i][3]);
        slab[(tx*8+0)*129 + br] = v0.x + bias[0];
        slab[(tx*8+1)*129 + br] = v0.y + bias[1];
        slab[(tx*8+2)*129 + br] = v1.x + bias[2];
        slab[(tx*8+3)*129 + br] = v1.y + bias[3];
        slab[(tx*8+4)*129 + br] = v2.x + bias[4];
        slab[(tx*8+5)*129 + br] = v2.y + bias[5];
        slab[(tx*8+6)*129 + br] = v3.x + bias[6];
        slab[(tx*8+7)*129 + br] = v3.y + bias[7];
    }
    __syncthreads();
    float* obase = xg + ((size_t)tBlk * G4 + nBase) * BB;
    for (int i = tid; i < 128 * 32; i += 256) {
        int g = i >> 5, c4 = (i & 31) << 2;
        float4 v = make_float4(slab[g*129+c4], slab[g*129+c4+1], slab[g*129+c4+2], slab[g*129+c4+3]);
        *(float4*)(obase + (size_t)g * BB + c4) = v;
    }
}

// ---- persistent LSTM recurrence: 128 CTAs, CTA bx owns h-cols [bx*4, bx*4+4) ----
__global__ __launch_bounds__(256, 1) void k_lstm(
    const float* __restrict__ Whh, const float* __restrict__ xg,
    float* __restrict__ hs)
{
    extern __shared__ float sm[];
    float (*w_s)[512] = (float(*)[512])sm;     // 16 x 512 (32 KB)
    float* hb0 = sm + 8192;                    // 128 x 132
    float* hb1 = sm + 8192 + 128 * 132;        // 128 x 132

    const int tid = threadIdx.x;
    const int bx = blockIdx.x;
    const int b = tid >> 1;
    const int half = tid & 1;
    const int w8 = half * 8;

    for (int i = tid; i < 16 * 512; i += 256) {
        int q = i >> 9, k = i & 511;
        int row = (q & 3) * HH + bx * 4 + (q >> 2);
        w_s[q][k] = Whh[(size_t)row * HH + k];
    }
    float c0 = 0.f, c1 = 0.f;
    __syncthreads();

    for (int t = 0; t < TT; t++) {
        // coalesced gate pre-activations from xg[t][g][b]
        const float* xgp = xg + (size_t)t * G4 * BB;
        float xv[8];
#pragma unroll
        for (int jl = 0; jl < 2; jl++)
#pragma unroll
            for (int g = 0; g < 4; g++)
                xv[jl * 4 + g] = __ldcg(xgp + (size_t)(g * HH + bx * 4 + half * 2 + jl) * BB + b);

        ull acc2[8];
#pragma unroll
        for (int q = 0; q < 8; q++) acc2[q] = 0ull;

        if (t > 0) {
            const float* hsrc = hs + (size_t)(t - 1) * BB * HH;
#pragma unroll
            for (int i = tid; i < 4096; i += 256) {
                int bl = i >> 5, k4 = (i & 31) << 2;
                *(float4*)&hb0[bl * 132 + k4] = __ldcg((const float4*)(hsrc + (size_t)bl * HH + k4));
            }
            __syncthreads();
            int buf = 0;
#pragma unroll
            for (int c = 0; c < 4; c++) {
                if (c < 3) {
                    float* dst = buf ? hb0 : hb1;
#pragma unroll
                    for (int i = tid; i < 4096; i += 256) {
                        int bl = i >> 5, k4 = (i & 31) << 2;
                        *(float4*)&dst[bl * 132 + k4] =
                            __ldcg((const float4*)(hsrc + (size_t)bl * HH + (c + 1) * 128 + k4));
                    }
                }
                const float* hbr = buf ? hb1 : hb0;
                const int kb = c * 128;
#pragma unroll 4
                for (int k = 0; k < 128; k += 4) {
                    ulonglong2 hv = *(const ulonglong2*)&hbr[b * 132 + k];
#pragma unroll
                    for (int q8 = 0; q8 < 8; q8++) {
                        ulonglong2 wv = *(const ulonglong2*)&w_s[w8 + q8][kb + k];
                        acc2[q8] = fma2(wv.x, hv.x, acc2[q8]);
                        acc2[q8] = fma2(wv.y, hv.y, acc2[q8]);
                    }
                }
                __syncthreads();
                buf ^= 1;
            }
        }

        float h0, h1;
        {
            float2 p;
            p = unpack2(acc2[0]); float gi = p.x + p.y + xv[0];
            p = unpack2(acc2[1]); float gf = p.x + p.y + xv[1];
            p = unpack2(acc2[2]); float gg = p.x + p.y + xv[2];
            p = unpack2(acc2[3]); float go = p.x + p.y + xv[3];
            float si = 1.f / (1.f + expf(-gi)), sf = 1.f / (1.f + expf(-gf));
            float so = 1.f / (1.f + expf(-go));
            c0 = sf * c0 + si * tanhf(gg);
            h0 = so * tanhf(c0);
            p = unpack2(acc2[4]); gi = p.x + p.y + xv[4];
            p = unpack2(acc2[5]); gf = p.x + p.y + xv[5];
            p = unpack2(acc2[6]); gg = p.x + p.y + xv[6];
            p = unpack2(acc2[7]); go = p.x + p.y + xv[7];
            si = 1.f / (1.f + expf(-gi)); sf = 1.f / (1.f + expf(-gf));
            so = 1.f / (1.f + expf(-go));
            c1 = sf * c1 + si * tanhf(gg);
            h1 = so * tanhf(c1);
        }
        float* hdst = hs + ((size_t)t * BB + b) * HH + bx * 4 + half * 2;
        __stcg(hdst, h0);
        __stcg(hdst + 1, h1);

        // flag-array grid barrier (all 128 CTAs resident)
        __threadfence();
        __syncthreads();
        if (tid == 0)
            *((volatile unsigned*)&g_flags[bx * 32]) = (unsigned)(t + 1);
        if (tid < 128) {
            volatile unsigned* fp = &g_flags[tid * 32];
            while (*fp < (unsigned)(t + 1)) { }
        }
        __threadfence();
        __syncthreads();
    }
}

// ---- r[b][g] = h_last[b][:] @ U1[g][512:1024] ----
__global__ __launch_bounds__(256) void k_r(
    const float* __restrict__ hs, const float* __restrict__ U1, float* __restrict__ r)
{
    __shared__ float hl[512];
    const int b = blockIdx.x, tid = threadIdx.x;
    for (int i = tid; i < 512; i += 256)
        hl[i] = hs[((size_t)(TT - 1) * BB + b) * HH + i];
    __syncthreads();
    for (int g = tid; g < 512; g += 256) {
        const float* up = U1 + (size_t)g * 1024 + 512;
        float acc = 0.f;
        for (int k = 0; k < 512; k += 4) {
            float4 u = *(const float4*)(up + k);
            acc += hl[k] * u.x + hl[k+1] * u.y + hl[k+2] * u.z + hl[k+3] * u.w;
        }
        r[(size_t)b * HH + g] = acc;
    }
}

// ---- e[m] += sum_g tanh(hs@U1a + x@U2 + r) * Ve[g] ----
__global__ __launch_bounds__(256, 2) void k_e(
    const float* __restrict__ hs, const float* __restrict__ x,
    const float* __restrict__ U1, const float* __restrict__ U2,
    const float* __restrict__ r, const float* __restrict__ Ve,
    float* __restrict__ e)
{
    __shared__ float As[2][8][132];
    __shared__ float Bs[2][8][132];
    const int tid = threadIdx.x;
    const int tx = tid & 15, ty = tid >> 4;
    const int mBase = blockIdx.y * 128, nBase = blockIdx.x * 128;
    const int lr = tid >> 1, lk = (tid & 1) * 4;
    const int m = mBase + lr;
    const float* aptrs[2] = { hs + (size_t)m * HH + lk,
                              x + ((size_t)(m & 127) * TT + (m >> 7)) * HH + lk };
    const float* bptrs[2] = { U1 + (size_t)(nBase + lr) * 1024 + lk,
                              U2 + (size_t)(nBase + lr) * 512 + lk };

    ull acc[8][4];
#pragma unroll
    for (int i = 0; i < 8; i++)
#pragma unroll
        for (int j = 0; j < 4; j++) acc[i][j] = 0ull;

    {
        float4 av = *(const float4*)aptrs[0];
        float4 bv = *(const float4*)bptrs[0];
        As[0][lk+0][lr]=av.x; As[0][lk+1][lr]=av.y; As[0][lk+2][lr]=av.z; As[0][lk+3][lr]=av.w;
        Bs[0][lk+0][lr]=bv.x; Bs[0][lk+1][lr]=bv.y; Bs[0][lk+2][lr]=bv.z; Bs[0][lk+3][lr]=bv.w;
    }
    __syncthreads();
    int buf = 0;

    for (int ph = 0; ph < 2; ph++) {
        const float* ap = aptrs[ph];
        const float* bp_ = bptrs[ph];
        for (int k0 = 0; k0 < HH; k0 += 8) {
            const bool last = (ph == 1) && (k0 + 8 >= HH);
            float4 av2, bv2;
            if (!last) {
                const float* an = (k0 + 8 < HH) ? ap + k0 + 8 : aptrs[1];
                const float* bn = (k0 + 8 < HH) ? bp_ + k0 + 8 : bptrs[1];
                av2 = *(const float4*)an;
                bv2 = *(const float4*)bn;
            }
#pragma unroll
            for (int k = 0; k < 8; k++) {
                float4 a0 = *(const float4*)&As[buf][k][ty * 8];
                float4 a1 = *(const float4*)&As[buf][k][ty * 8 + 4];
                ulonglong2 b0 = *(const ulonglong2*)&Bs[buf][k][tx * 8];
                ulonglong2 b1 = *(const ulonglong2*)&Bs[buf][k][tx * 8 + 4];
                float af[8] = {a0.x, a0.y, a0.z, a0.w, a1.x, a1.y, a1.z, a1.w};
                ull bp2[4] = {b0.x, b0.y, b1.x, b1.y};
#pragma unroll
                for (int i = 0; i < 8; i++) {
                    ull apk = pack2(af[i], af[i]);
#pragma unroll
                    for (int j = 0; j < 4; j++) acc[i][j] = fma2(apk, bp2[j], acc[i][j]);
                }
            }
            if (!last) {
                int nb = buf ^ 1;
                As[nb][lk+0][lr]=av2.x; As[nb][lk+1][lr]=av2.y; As[nb][lk+2][lr]=av2.z; As[nb][lk+3][lr]=av2.w;
                Bs[nb][lk+0][lr]=bv2.x; Bs[nb][lk+1][lr]=bv2.y; Bs[nb][lk+2][lr]=bv2.z; Bs[nb][lk+3][lr]=bv2.w;
            }
            __syncthreads();
            buf ^= 1;
        }
    }

    const int gc = nBase + tx * 8;
    float ve[8];
#pragma unroll
    for (int j = 0; j < 8; j++) ve[j] = Ve[gc + j];
#pragma unroll
    for (int i = 0; i < 8; i++) {
        const int brow = ty * 8 + i;
        const float* rr = r + (size_t)brow * HH + gc;
        float si = 0.f; float2 v;
        v = unpack2(acc[i][0]); si += tanhf(v.x + rr[0]) * ve[0] + tanhf(v.y + rr[1]) * ve[1];
        v = unpack2(acc[i][1]); si += tanhf(v.x + rr[2]) * ve[2] + tanhf(v.y + rr[3]) * ve[3];
        v = unpack2(acc[i][2]); si += tanhf(v.x + rr[4]) * ve[4] + tanhf(v.y + rr[5]) * ve[5];
        v = unpack2(acc[i][3]); si += tanhf(v.x + rr[6]) * ve[6] + tanhf(v.y + rr[7]) * ve[7];
#pragma unroll
        for (int o = 8; o >= 1; o >>= 1)
            si += __shfl_xor_sync(0xffffffffu, si, o, 16);
        if (tx == 0) atomicAdd(&e[mBase + ty * 8 + i], si);
    }
}

// ---- softmax over t, context, output head; one CTA per batch element ----
__global__ __launch_bounds__(256) void k_final(
    const float* __restrict__ hs, const float* __restrict__ e,
    const float* __restrict__ Wout, const float* __restrict__ bout,
    float* __restrict__ out)
{
    __shared__ float al[512];
    __shared__ float red[256];
    const int b = blockIdx.x, tid = threadIdx.x;

    float ev0 = e[(size_t)tid * BB + b];
    float ev1 = e[(size_t)(tid + 256) * BB + b];

    red[tid] = fmaxf(ev0, ev1);
    __syncthreads();
    for (int s = 128; s > 0; s >>= 1) {
        if (tid < s) red[tid] = fmaxf(red[tid], red[tid + s]);
        __syncthreads();
    }
    float mx = red[0];
    __syncthreads();
    float x0 = expf(ev0 - mx), x1 = expf(ev1 - mx);
    red[tid] = x0 + x1;
    __syncthreads();
    for (int s = 128; s > 0; s >>= 1) {
        if (tid < s) red[tid] += red[tid + s];
        __syncthreads();
    }
    float inv = 1.f / red[0];
    al[tid] = x0 * inv;
    al[tid + 256] = x1 * inv;
    __syncthreads();

    float ctx0 = 0.f, ctx1 = 0.f;
    for (int t = 0; t < TT; t++) {
        float a = al[t];
        const float* hp = hs + ((size_t)t * BB + b) * HH;
        ctx0 += a * hp[tid];
        ctx1 += a * hp[tid + 256];
    }

    float p0 = ctx0 * Wout[tid] + ctx1 * Wout[tid + 256];
    float p1 = ctx0 * Wout[512 + tid] + ctx1 * Wout[512 + tid + 256];
    red[tid] = p0;
    __syncthreads();
    for (int s = 128; s > 0; s >>= 1) {
        if (tid < s) red[tid] += red[tid + s];
        __syncthreads();
    }
    float mu = red[0] + bout[0];
    __syncthreads();
    red[tid] = p1;
    __syncthreads();
    for (int s = 128; s > 0; s >>= 1) {
        if (tid < s) red[tid] += red[tid + s];
        __syncthreads();
    }
    if (tid == 0) {
        float pv = red[0] + bout[1];
        float sp = (pv > 20.f) ? pv : log1pf(expf(pv));
        out[b] = mu;
        out[BB + b] = sp + 1e-5f;
    }
}

extern "C" void kernel_launch(void* const* d_in, const int* in_sizes, int n_in,
                              void* d_out, int out_size) {
    const float* x    = (const float*)d_in[0];
    const float* Wih  = (const float*)d_in[1];
    const float* Whh  = (const float*)d_in[2];
    const float* bih  = (const float*)d_in[3];
    const float* bhh  = (const float*)d_in[4];
    const float* Ve   = (const float*)d_in[5];
    const float* U1   = (const float*)d_in[6];
    const float* U2   = (const float*)d_in[7];
    const float* Wout = (const float*)d_in[8];
    const float* bout = (const float*)d_in[9];
    float* out = (float*)d_out;

    float *xg, *hs, *r, *e;
    cudaGetSymbolAddress((void**)&xg, g_xg);
    cudaGetSymbolAddress((void**)&hs, g_hs);
    cudaGetSymbolAddress((void**)&r,  g_r);
    cudaGetSymbolAddress((void**)&e,  g_e);

    cudaFuncSetAttribute(k_xg,   cudaFuncAttributeMaxDynamicSharedMemorySize, 128 * 129 * 4);
    cudaFuncSetAttribute(k_lstm, cudaFuncAttributeMaxDynamicSharedMemorySize, (8192 + 2 * 128 * 132) * 4);

    k_init<<<(TT * BB + 255) / 256, 256>>>(e);
    {
        dim3 g(G4 / 128, TT);
        k_xg<<<g, 256, 128 * 129 * 4>>>(x, Wih, bih, bhh, xg);
    }
    k_lstm<<<128, 256, (8192 + 2 * 128 * 132) * 4>>>(Whh, xg, hs);
    k_r<<<BB, 256>>>(hs, U1, r);
    {
        dim3 g(HH / 128, (TT * BB) / 128);
        k_e<<<g, 256>>>(hs, x, U1, U2, r, Ve, e);
    }
    k_final<<<BB, 256>>>(hs, e, Wout, bout, out);
}